// round 3
// baseline (speedup 1.0000x reference)
#include <cuda_runtime.h>

#define SEQ     8192
#define HIDDEN  1024
#define NHEADS  16
#define HDIM    64
#define CHUNK   128            // queries per block
#define NCHUNK  (SEQ / CHUNK)  // 64
#define TILE    128            // keys per tile
#define THREADS 256

typedef unsigned long long ull;

// ---- packed f32x2 helpers (Blackwell) ----
__device__ __forceinline__ ull pk2(float lo, float hi) {
    ull r; asm("mov.b64 %0,{%1,%2};" : "=l"(r) : "f"(lo), "f"(hi)); return r;
}
__device__ __forceinline__ void upk2(ull v, float& lo, float& hi) {
    asm("mov.b64 {%0,%1},%2;" : "=f"(lo), "=f"(hi) : "l"(v));
}
__device__ __forceinline__ ull fma2(ull a, ull b, ull c) {
    ull d; asm("fma.rn.f32x2 %0,%1,%2,%3;" : "=l"(d) : "l"(a), "l"(b), "l"(c)); return d;
}

// smem layout (float offsets)
#define QT_OFF   0                         // Q^T [64][132]
#define KT_OFF   (QT_OFF + 64 * 132)       // K^T [64][132]
#define VS_OFF   (KT_OFF + 64 * 132)       // V   [128][64]
#define PT_OFF   (VS_OFF + 128 * 64)       // P^T [128][132]  (probs, [key][query])
#define LB_OFF   (PT_OFF + 128 * 132)      // lbuf [16][132]  (row-sum partials per tx)
#define LI_OFF   (LB_OFF + 16 * 132)       // linv [128]
#define SMEM_FLOATS (LI_OFF + 128)         // 44224 floats = 176896 B

// Block = (batch, head, 128-query chunk). 256 threads.
// Per 128-key tile: GEMM1 (scores, 8x8/thread) -> mask+exp -> P^T smem -> GEMM2 (8qx4d/thread).
__global__ void __launch_bounds__(THREADS, 1)
swa2_kernel(const float* __restrict__ Q, const float* __restrict__ K,
            const float* __restrict__ V, float* __restrict__ O) {
    extern __shared__ float sm[];

    const int tid = threadIdx.x;
    const int c = blockIdx.x & (NCHUNK - 1);
    const int h = (blockIdx.x >> 6) & (NHEADS - 1);
    const int b = blockIdx.x >> 10;

    const int tx = tid & 15;      // GEMM1: key-group; GEMM2: d-group
    const int ty = tid >> 4;      // query-group (8 queries)

    // zero lbuf
    for (int i = tid; i < 16 * 132; i += THREADS) sm[LB_OFF + i] = 0.f;

    // ---- load Q chunk transposed: QT[d][q], coalesced LDG
    {
        const int d4 = tid & 15;
        const int q0 = (tid >> 4) * 8;
        const float4* Q4 = (const float4*)Q +
            ((size_t)b * SEQ + c * CHUNK) * (HIDDEN / 4) + h * (HDIM / 4) + d4;
        #pragma unroll
        for (int a = 0; a < 8; a++) {
            float4 v = Q4[(size_t)(q0 + a) * (HIDDEN / 4)];
            sm[QT_OFF + (4 * d4 + 0) * 132 + q0 + a] = v.x;
            sm[QT_OFF + (4 * d4 + 1) * 132 + q0 + a] = v.y;
            sm[QT_OFF + (4 * d4 + 2) * 132 + q0 + a] = v.z;
            sm[QT_OFF + (4 * d4 + 3) * 132 + q0 + a] = v.w;
        }
    }

    // persistent output accumulators: 8 queries x 4 dims (2 f32x2 pairs)
    ull oacc[8][2];
    #pragma unroll
    for (int a = 0; a < 8; a++) { oacc[a][0] = 0ull; oacc[a][1] = 0ull; }

    for (int kt = 0; kt < 3; kt++) {
        if ((kt == 0 && c == 0) || (kt == 2 && c == NCHUNK - 1)) continue;
        __syncthreads();   // prior GEMM2 done (and Q/lbuf stores visible) before refilling KT/VS

        const int kbase = c * CHUNK - CHUNK + kt * TILE;   // global key of tile row 0

        // ---- load K tile transposed: KT[d][k]
        {
            const int d4 = tid & 15;
            const int k0 = (tid >> 4) * 8;
            #pragma unroll
            for (int a = 0; a < 8; a++) {
                const int kp = kbase + k0 + a;
                float4 v = make_float4(0.f, 0.f, 0.f, 0.f);
                if ((unsigned)kp < SEQ)
                    v = ((const float4*)K)[((size_t)b * SEQ + kp) * (HIDDEN / 4) + h * (HDIM / 4) + d4];
                sm[KT_OFF + (4 * d4 + 0) * 132 + k0 + a] = v.x;
                sm[KT_OFF + (4 * d4 + 1) * 132 + k0 + a] = v.y;
                sm[KT_OFF + (4 * d4 + 2) * 132 + k0 + a] = v.z;
                sm[KT_OFF + (4 * d4 + 3) * 132 + k0 + a] = v.w;
            }
            // ---- load V tile natural: VS[k][d]
            #pragma unroll
            for (int i = 0; i < 8; i++) {
                const int idx = tid + i * THREADS;
                const int row = idx >> 4, c4 = idx & 15;
                const int kp = kbase + row;
                float4 v = make_float4(0.f, 0.f, 0.f, 0.f);
                if ((unsigned)kp < SEQ)
                    v = ((const float4*)V)[((size_t)b * SEQ + kp) * (HIDDEN / 4) + h * (HDIM / 4) + c4];
                ((float4*)(sm + VS_OFF))[idx] = v;
            }
        }
        __syncthreads();

        // ---- GEMM1: S(8q x 8k) per thread, d streamed from smem
        ull s2[8][4];
        #pragma unroll
        for (int a = 0; a < 8; a++)
            #pragma unroll
            for (int bb = 0; bb < 4; bb++) s2[a][bb] = 0ull;

        #pragma unroll 4
        for (int d = 0; d < HDIM; d++) {
            const float4 a0 = *(const float4*)(sm + QT_OFF + d * 132 + 8 * ty);
            const float4 a1 = *(const float4*)(sm + QT_OFF + d * 132 + 8 * ty + 4);
            const ulonglong2 b0 = *(const ulonglong2*)(sm + KT_OFF + d * 132 + 8 * tx);
            const ulonglong2 b1 = *(const ulonglong2*)(sm + KT_OFF + d * 132 + 8 * tx + 4);
            const float A[8] = {a0.x, a0.y, a0.z, a0.w, a1.x, a1.y, a1.z, a1.w};
            #pragma unroll
            for (int a = 0; a < 8; a++) {
                const ull aa = pk2(A[a], A[a]);
                s2[a][0] = fma2(aa, b0.x, s2[a][0]);
                s2[a][1] = fma2(aa, b0.y, s2[a][1]);
                s2[a][2] = fma2(aa, b1.x, s2[a][2]);
                s2[a][3] = fma2(aa, b1.y, s2[a][3]);
            }
        }

        // ---- mask + exp (no-max softmax: exact, scores bounded), row-sum partials
        float p[8][8];
        const int jjb = kt * TILE + 8 * tx;       // window coord of kk=0
        const int kg0 = kbase + 8 * tx;           // global key pos of kk=0
        #pragma unroll
        for (int a = 0; a < 8; a++) {
            const int i = 8 * ty + a;             // local query index
            float lsum = 0.f;
            #pragma unroll
            for (int bb = 0; bb < 4; bb++) {
                float s0, s1; upk2(s2[a][bb], s0, s1);
                const int kk0 = 2 * bb, kk1 = 2 * bb + 1;
                const int jj0 = jjb + kk0, jj1 = jjb + kk1;
                const bool v0 = (jj0 >= i) && (jj0 <= i + 256) && ((unsigned)(kg0 + kk0) < SEQ);
                const bool v1 = (jj1 >= i) && (jj1 <= i + 256) && ((unsigned)(kg0 + kk1) < SEQ);
                const float p0 = v0 ? __expf(s0) : 0.f;
                const float p1 = v1 ? __expf(s1) : 0.f;
                p[a][kk0] = p0; p[a][kk1] = p1;
                lsum += p0 + p1;
            }
            sm[LB_OFF + tx * 132 + i] += lsum;    // unique (tx, i) per thread: race-free
        }
        // store probs transposed: PT[key][query]
        #pragma unroll
        for (int kk = 0; kk < 8; kk++) {
            const int row = 8 * tx + kk;
            *(float4*)(sm + PT_OFF + row * 132 + 8 * ty) =
                make_float4(p[0][kk], p[1][kk], p[2][kk], p[3][kk]);
            *(float4*)(sm + PT_OFF + row * 132 + 8 * ty + 4) =
                make_float4(p[4][kk], p[5][kk], p[6][kk], p[7][kk]);
        }
        __syncthreads();

        // ---- GEMM2: O(8q x 4d) += P(8q x j) * V(j x 4d), band-shortened j range
        const int jlo = (kt == 0) ? 8 * ty : 0;
        const int jhi = (kt == 2) ? 8 * ty + 8 : TILE;
        #pragma unroll 2
        for (int j = jlo; j < jhi; j++) {
            const float4 pa0 = *(const float4*)(sm + PT_OFF + j * 132 + 8 * ty);
            const float4 pa1 = *(const float4*)(sm + PT_OFF + j * 132 + 8 * ty + 4);
            const ulonglong2 vv = *(const ulonglong2*)(sm + VS_OFF + j * 64 + 4 * tx);
            const float P8[8] = {pa0.x, pa0.y, pa0.z, pa0.w, pa1.x, pa1.y, pa1.z, pa1.w};
            #pragma unroll
            for (int a = 0; a < 8; a++) {
                const ull pp = pk2(P8[a], P8[a]);
                oacc[a][0] = fma2(pp, vv.x, oacc[a][0]);
                oacc[a][1] = fma2(pp, vv.y, oacc[a][1]);
            }
        }
    }

    __syncthreads();
    // ---- reduce row sums, invert
    if (tid < CHUNK) {
        float s = 0.f;
        #pragma unroll
        for (int x = 0; x < 16; x++) s += sm[LB_OFF + x * 132 + tid];
        sm[LI_OFF + tid] = 1.f / s;
    }
    __syncthreads();

    // ---- normalize + write out (coalesced float4)
    #pragma unroll
    for (int a = 0; a < 8; a++) {
        const int q = 8 * ty + a;
        const float inv = sm[LI_OFF + q];
        float o0, o1, o2, o3;
        upk2(oacc[a][0], o0, o1);
        upk2(oacc[a][1], o2, o3);
        const float4 o = make_float4(o0 * inv, o1 * inv, o2 * inv, o3 * inv);
        ((float4*)O)[((size_t)b * SEQ + c * CHUNK + q) * (HIDDEN / 4) + h * (HDIM / 4) + tx] = o;
    }
}

extern "C" void kernel_launch(void* const* d_in, const int* in_sizes, int n_in,
                              void* d_out, int out_size) {
    const float* Q = (const float*)d_in[0];
    const float* K = (const float*)d_in[1];
    const float* V = (const float*)d_in[2];
    float* O = (float*)d_out;

    const int smem = SMEM_FLOATS * (int)sizeof(float);   // 176896 B
    cudaFuncSetAttribute(swa2_kernel, cudaFuncAttributeMaxDynamicSharedMemorySize, smem);

    dim3 grid(2 * NHEADS * NCHUNK);   // 2048 blocks: (b, h, chunk)
    swa2_kernel<<<grid, THREADS, smem>>>(Q, K, V, O);
}

// round 10
// speedup vs baseline: 2.4584x; 2.4584x over previous
#include <cuda_runtime.h>
#include <cuda_bf16.h>
#include <cstdint>

#define SEQ     8192
#define HID     1024
#define NCHUNK  64
#define THREADS 256

// smem: 6 bf16 tiles [128 rows][64 d], 128 B/row, SW128-swizzled (16 KB each)
#define OF_QH 0
#define OF_QL 16384
#define OF_KH 32768
#define OF_KL 49152
#define OF_VH 65536
#define OF_VL 81920
#define SMEM_TOTAL 98304

__device__ __forceinline__ uint32_t smem_u32(const void* p) {
    uint32_t a;
    asm("{ .reg .u64 t; cvta.to.shared.u64 t, %1; cvt.u32.u64 %0, t; }" : "=r"(a) : "l"(p));
    return a;
}
__device__ __forceinline__ uint32_t SWZ(uint32_t x) { return x ^ ((x >> 3) & 0x70); }

__device__ __forceinline__ void ldsm4(uint32_t* r, uint32_t a) {
    asm volatile("ldmatrix.sync.aligned.m8n8.x4.shared.b16 {%0,%1,%2,%3}, [%4];"
        : "=r"(r[0]), "=r"(r[1]), "=r"(r[2]), "=r"(r[3]) : "r"(a));
}
__device__ __forceinline__ void ldsm4t(uint32_t* r, uint32_t a) {
    asm volatile("ldmatrix.sync.aligned.m8n8.x4.trans.shared.b16 {%0,%1,%2,%3}, [%4];"
        : "=r"(r[0]), "=r"(r[1]), "=r"(r[2]), "=r"(r[3]) : "r"(a));
}
__device__ __forceinline__ void mma_bf16(float* c, const uint32_t* a, uint32_t b0, uint32_t b1) {
    asm volatile("mma.sync.aligned.m16n8k16.row.col.f32.bf16.bf16.f32 "
        "{%0,%1,%2,%3}, {%4,%5,%6,%7}, {%8,%9}, {%0,%1,%2,%3};"
        : "+f"(c[0]), "+f"(c[1]), "+f"(c[2]), "+f"(c[3])
        : "r"(a[0]), "r"(a[1]), "r"(a[2]), "r"(a[3]), "r"(b0), "r"(b1));
}
// pack two floats to bf16x2: lo -> bits[15:0], hi -> bits[31:16]
__device__ __forceinline__ uint32_t pk_bf16(float lo, float hi) {
    uint32_t r; asm("cvt.rn.bf16x2.f32 %0, %1, %2;" : "=r"(r) : "f"(hi), "f"(lo)); return r;
}
// error-split a pair of floats into bf16x2 hi + bf16x2 lo(residual)
__device__ __forceinline__ void split2(float a, float b, uint32_t& hi, uint32_t& lo) {
    hi = pk_bf16(a, b);
    float ra = a - __uint_as_float(hi << 16);
    float rb = b - __uint_as_float(hi & 0xffff0000u);
    lo = pk_bf16(ra, rb);
}

// Load [128 rows][64 d] fp32 tile from gmem, split to bf16 hi/lo, store SW128-swizzled.
__device__ __forceinline__ void load_split(const float4* g, char* smh, char* sml, int tid) {
    const int dg = tid & 7;        // 8-float d-group
    const int r0 = tid >> 3;       // 0..31
    #pragma unroll
    for (int rr = 0; rr < 4; rr++) {
        const int r = r0 + rr * 32;
        const float4* gp = g + (size_t)r * (HID / 4) + dg * 2;
        const float4 x0 = gp[0], x1 = gp[1];
        uint4 uh, ul;
        split2(x0.x, x0.y, uh.x, ul.x);
        split2(x0.z, x0.w, uh.y, ul.y);
        split2(x1.x, x1.y, uh.z, ul.z);
        split2(x1.z, x1.w, uh.w, ul.w);
        const uint32_t so = SWZ((uint32_t)(r * 128 + dg * 16));
        *(uint4*)(smh + so) = uh;
        *(uint4*)(sml + so) = ul;
    }
}

// Block = (batch, head, 128-query chunk). 8 warps; warp w owns query rows [16w,16w+16).
// Per 128-key tile: QK^T (HMMA, 3-term bf16 split) -> mask+exp in regs -> split P ->
// PV (HMMA, V via ldmatrix.trans). O accumulates in fp32 fragments (no-max softmax).
__global__ void __launch_bounds__(THREADS, 1)
swa_hmma_kernel(const float* __restrict__ Q, const float* __restrict__ K,
                const float* __restrict__ V, float* __restrict__ O) {
    extern __shared__ char sm[];
    const uint32_t sb = smem_u32(sm);
    const int tid = threadIdx.x;
    const int w = tid >> 5, t = tid & 31;
    const int c = blockIdx.x & (NCHUNK - 1);
    const int h = (blockIdx.x >> 6) & 15;
    const int b = blockIdx.x >> 10;

    // ---- Q chunk -> smem (hi/lo), then A-fragments into registers
    load_split((const float4*)Q + ((size_t)b * SEQ + c * 128) * (HID / 4) + h * 16,
               sm + OF_QH, sm + OF_QL, tid);
    __syncthreads();

    uint32_t qh[4][4], ql[4][4];
    {
        const uint32_t rowb = (uint32_t)((16 * w + (t & 15)) * 128 + ((t >> 4) & 1) * 16);
        #pragma unroll
        for (int kk = 0; kk < 4; kk++) {
            const uint32_t off = SWZ(rowb + kk * 32);
            ldsm4(qh[kk], sb + OF_QH + off);
            ldsm4(ql[kk], sb + OF_QL + off);
        }
    }

    float oacc[8][4];
    #pragma unroll
    for (int j = 0; j < 8; j++)
        #pragma unroll
        for (int r = 0; r < 4; r++) oacc[j][r] = 0.f;
    float l0 = 0.f, l1 = 0.f;
    const int i0 = 16 * w + (t >> 2);      // first query row of this thread

    const int ktA = (c == 0) ? 1 : 0;
    const int ktB = (c == NCHUNK - 1) ? 1 : 2;

    for (int kt = ktA; kt <= ktB; kt++) {
        __syncthreads();   // previous tile's ldmatrix reads done before overwrite
        const int kbase = c * 128 - 128 + kt * 128;   // fully in-range (edge tiles skipped)
        load_split((const float4*)K + ((size_t)b * SEQ + kbase) * (HID / 4) + h * 16,
                   sm + OF_KH, sm + OF_KL, tid);
        load_split((const float4*)V + ((size_t)b * SEQ + kbase) * (HID / 4) + h * 16,
                   sm + OF_VH, sm + OF_VL, tid);
        __syncthreads();

        // band-aware kstep bounds (warp-uniform): 16-key group g useful iff it
        // intersects [16w, 16w+15+256] window for this warp's rows
        const int glo = (kt == 0) ? w : 0;
        const int ghi = (kt == 2) ? w : 7;

        float acc[16][4];
        #pragma unroll
        for (int n = 0; n < 16; n++)
            #pragma unroll
            for (int r = 0; r < 4; r++) acc[n][r] = 0.f;

        // ---- GEMM1: S[16q][128k] = Qh*Kh + Qh*Kl + Ql*Kh
        {
            const uint32_t rb = (uint32_t)(((t & 7) + ((t >> 4) & 1) * 8) * 128 + ((t >> 3) & 1) * 16);
            #pragma unroll
            for (int kk = 0; kk < 4; kk++) {
                #pragma unroll
                for (int g = 0; g < 8; g++) {
                    if (g < glo || g > ghi) continue;
                    const uint32_t off = SWZ(rb + g * 2048 + kk * 32);
                    uint32_t bh[4], bl[4];
                    ldsm4(bh, sb + OF_KH + off);
                    ldsm4(bl, sb + OF_KL + off);
                    mma_bf16(acc[2 * g],     qh[kk], bh[0], bh[1]);
                    mma_bf16(acc[2 * g],     qh[kk], bl[0], bl[1]);
                    mma_bf16(acc[2 * g],     ql[kk], bh[0], bh[1]);
                    mma_bf16(acc[2 * g + 1], qh[kk], bh[2], bh[3]);
                    mma_bf16(acc[2 * g + 1], qh[kk], bl[2], bl[3]);
                    mma_bf16(acc[2 * g + 1], ql[kk], bh[2], bh[3]);
                }
            }
        }

        // ---- mask + exp (no-max softmax: exact; scores bounded) in registers
        #pragma unroll
        for (int nt = 0; nt < 16; nt++) {
            if (nt < 2 * glo || nt > 2 * ghi + 1) continue;
            const int cb = kt * 128 + 8 * nt + 2 * (t & 3);   // window coord of reg0
            const int iB = i0 + 8;
            const float p0 = (cb     >= i0 && cb     <= i0 + 256) ? __expf(acc[nt][0]) : 0.f;
            const float p1 = (cb + 1 >= i0 && cb + 1 <= i0 + 256) ? __expf(acc[nt][1]) : 0.f;
            const float p2 = (cb     >= iB && cb     <= iB + 256) ? __expf(acc[nt][2]) : 0.f;
            const float p3 = (cb + 1 >= iB && cb + 1 <= iB + 256) ? __expf(acc[nt][3]) : 0.f;
            acc[nt][0] = p0; acc[nt][1] = p1; acc[nt][2] = p2; acc[nt][3] = p3;
            l0 += p0 + p1;
            l1 += p2 + p3;
        }

        // ---- GEMM2: O[16q][64d] += Ph*Vh + Ph*Vl + Pl*Vh  (P split in regs)
        {
            const uint32_t vb = (uint32_t)(((t & 7) + ((t >> 3) & 1) * 8) * 128 + ((t >> 4) & 1) * 16);
            #pragma unroll
            for (int s = 0; s < 8; s++) {
                if (s < glo || s > ghi) continue;
                uint32_t pah[4], pal[4];
                split2(acc[2 * s][0],     acc[2 * s][1],     pah[0], pal[0]);
                split2(acc[2 * s][2],     acc[2 * s][3],     pah[1], pal[1]);
                split2(acc[2 * s + 1][0], acc[2 * s + 1][1], pah[2], pal[2]);
                split2(acc[2 * s + 1][2], acc[2 * s + 1][3], pah[3], pal[3]);
                #pragma unroll
                for (int u = 0; u < 4; u++) {
                    const uint32_t off = SWZ(vb + s * 2048 + u * 32);
                    uint32_t vh[4], vl[4];
                    ldsm4t(vh, sb + OF_VH + off);
                    ldsm4t(vl, sb + OF_VL + off);
                    mma_bf16(oacc[2 * u],     pah, vh[0], vh[1]);
                    mma_bf16(oacc[2 * u],     pah, vl[0], vl[1]);
                    mma_bf16(oacc[2 * u],     pal, vh[0], vh[1]);
                    mma_bf16(oacc[2 * u + 1], pah, vh[2], vh[3]);
                    mma_bf16(oacc[2 * u + 1], pah, vl[2], vl[3]);
                    mma_bf16(oacc[2 * u + 1], pal, vh[2], vh[3]);
                }
            }
        }
    }

    // ---- reduce row sums within the quad that shares these rows
    l0 += __shfl_xor_sync(0xffffffffu, l0, 1);
    l0 += __shfl_xor_sync(0xffffffffu, l0, 2);
    l1 += __shfl_xor_sync(0xffffffffu, l1, 1);
    l1 += __shfl_xor_sync(0xffffffffu, l1, 2);
    const float inv0 = 1.f / l0, inv1 = 1.f / l1;

    // ---- normalize + write (float2 per fragment pair)
    float* Ob = O + ((size_t)b * SEQ + c * 128) * HID + h * 64;
    const int dcol = 2 * (t & 3);
    #pragma unroll
    for (int j = 0; j < 8; j++) {
        float2 v0 = make_float2(oacc[j][0] * inv0, oacc[j][1] * inv0);
        float2 v1 = make_float2(oacc[j][2] * inv1, oacc[j][3] * inv1);
        *(float2*)(Ob + (size_t)i0 * HID + 8 * j + dcol) = v0;
        *(float2*)(Ob + (size_t)(i0 + 8) * HID + 8 * j + dcol) = v1;
    }
}

extern "C" void kernel_launch(void* const* d_in, const int* in_sizes, int n_in,
                              void* d_out, int out_size) {
    const float* Q = (const float*)d_in[0];
    const float* K = (const float*)d_in[1];
    const float* V = (const float*)d_in[2];
    float* O = (float*)d_out;

    cudaFuncSetAttribute(swa_hmma_kernel, cudaFuncAttributeMaxDynamicSharedMemorySize, SMEM_TOTAL);
    dim3 grid(2 * 16 * NCHUNK);   // 2048 blocks: (b, h, chunk)
    swa_hmma_kernel<<<grid, THREADS, SMEM_TOTAL>>>(Q, K, V, O);
}

// round 12
// speedup vs baseline: 2.7766x; 1.1294x over previous
#include <cuda_runtime.h>
#include <cuda_bf16.h>
#include <cstdint>

#define SEQ     8192
#define HID     1024
#define NCHUNK  64
#define THREADS 256

// smem: 6 bf16 tiles [128 rows][64 d] SW128 (16 KB each) + fp32 K/V staging (32 KB each)
#define OF_QH 0
#define OF_QL 16384
#define OF_KH 32768
#define OF_KL 49152
#define OF_VH 65536
#define OF_VL 81920
#define OF_SK 98304
#define OF_SV 131072
#define SMEM_TOTAL 163840

__device__ __forceinline__ uint32_t smem_u32(const void* p) {
    uint32_t a;
    asm("{ .reg .u64 t; cvta.to.shared.u64 t, %1; cvt.u32.u64 %0, t; }" : "=r"(a) : "l"(p));
    return a;
}
__device__ __forceinline__ uint32_t SWZ(uint32_t x) { return x ^ ((x >> 3) & 0x70); }

__device__ __forceinline__ void ldsm4(uint32_t* r, uint32_t a) {
    asm volatile("ldmatrix.sync.aligned.m8n8.x4.shared.b16 {%0,%1,%2,%3}, [%4];"
        : "=r"(r[0]), "=r"(r[1]), "=r"(r[2]), "=r"(r[3]) : "r"(a));
}
__device__ __forceinline__ void ldsm4t(uint32_t* r, uint32_t a) {
    asm volatile("ldmatrix.sync.aligned.m8n8.x4.trans.shared.b16 {%0,%1,%2,%3}, [%4];"
        : "=r"(r[0]), "=r"(r[1]), "=r"(r[2]), "=r"(r[3]) : "r"(a));
}
__device__ __forceinline__ void mma_bf16(float* c, const uint32_t* a, uint32_t b0, uint32_t b1) {
    asm volatile("mma.sync.aligned.m16n8k16.row.col.f32.bf16.bf16.f32 "
        "{%0,%1,%2,%3}, {%4,%5,%6,%7}, {%8,%9}, {%0,%1,%2,%3};"
        : "+f"(c[0]), "+f"(c[1]), "+f"(c[2]), "+f"(c[3])
        : "r"(a[0]), "r"(a[1]), "r"(a[2]), "r"(a[3]), "r"(b0), "r"(b1));
}
__device__ __forceinline__ uint32_t pk_bf16(float lo, float hi) {
    uint32_t r; asm("cvt.rn.bf16x2.f32 %0, %1, %2;" : "=r"(r) : "f"(hi), "f"(lo)); return r;
}
__device__ __forceinline__ void split2(float a, float b, uint32_t& hi, uint32_t& lo) {
    hi = pk_bf16(a, b);
    float ra = a - __uint_as_float(hi << 16);
    float rb = b - __uint_as_float(hi & 0xffff0000u);
    lo = pk_bf16(ra, rb);
}
#define CP_COMMIT() asm volatile("cp.async.commit_group;" ::: "memory")
#define CP_WAIT0()  asm volatile("cp.async.wait_group 0;" ::: "memory")
__device__ __forceinline__ void cp16(uint32_t s, const void* g) {
    asm volatile("cp.async.cg.shared.global [%0], [%1], 16;" :: "r"(s), "l"(g));
}

// issue async copy of one K tile + one V tile (fp32, [128 rows][64 d]) into staging
__device__ __forceinline__ void issue_cp_tile(uint32_t sb, const float* Kg, const float* Vg, int tid) {
    #pragma unroll
    for (int i = 0; i < 8; i++) {
        const int idx = tid + i * THREADS;
        const int r = idx >> 4, c4 = idx & 15;
        cp16(sb + OF_SK + idx * 16, Kg + (size_t)r * HID + c4 * 4);
        cp16(sb + OF_SV + idx * 16, Vg + (size_t)r * HID + c4 * 4);
    }
}

// fp32 staging (smem) -> bf16 hi/lo SW128 tiles. Conflict-free: thread reads
// float4 slots dg and dg+8 of a row (8 lanes x 16B = 32 distinct banks / phase).
__device__ __forceinline__ void convert_tile(const float* stage, char* smh, char* sml, int tid) {
    const int dg = tid & 7;
    const int r0 = tid >> 3;
    #pragma unroll
    for (int rr = 0; rr < 4; rr++) {
        const int r = r0 + rr * 32;
        const float4* sp = (const float4*)stage + r * 16;
        const float4 x0 = sp[dg];
        const float4 x1 = sp[dg + 8];
        uint2 h0, l0, h1, l1;
        split2(x0.x, x0.y, h0.x, l0.x);
        split2(x0.z, x0.w, h0.y, l0.y);
        split2(x1.x, x1.y, h1.x, l1.x);
        split2(x1.z, x1.w, h1.y, l1.y);
        const uint32_t s0 = SWZ((uint32_t)(r * 128 + dg * 8));
        const uint32_t s1 = SWZ((uint32_t)(r * 128 + 64 + dg * 8));
        *(uint2*)(smh + s0) = h0; *(uint2*)(sml + s0) = l0;
        *(uint2*)(smh + s1) = h1; *(uint2*)(sml + s1) = l1;
    }
}

// direct-LDG variant for Q (once per block)
__device__ __forceinline__ void load_split_q(const float4* g, char* smh, char* sml, int tid) {
    const int dg = tid & 7;
    const int r0 = tid >> 3;
    #pragma unroll
    for (int rr = 0; rr < 4; rr++) {
        const int r = r0 + rr * 32;
        const float4* gp = g + (size_t)r * (HID / 4) + dg * 2;
        const float4 x0 = gp[0], x1 = gp[1];
        uint4 uh, ul;
        split2(x0.x, x0.y, uh.x, ul.x);
        split2(x0.z, x0.w, uh.y, ul.y);
        split2(x1.x, x1.y, uh.z, ul.z);
        split2(x1.z, x1.w, uh.w, ul.w);
        const uint32_t so = SWZ((uint32_t)(r * 128 + dg * 16));
        *(uint4*)(smh + so) = uh;
        *(uint4*)(sml + so) = ul;
    }
}

// Block = (batch, head, 128-query chunk). 8 warps; warp w owns query rows [16w,16w+16).
// Pipeline: cp.async prefetch of next K/V tile overlaps current tile's GEMMs.
// Per 16-key group: QK HMMAs -> mask+exp -> split P -> PV HMMAs (fused for ILP).
__global__ void __launch_bounds__(THREADS, 1)
swa_hmma2_kernel(const float* __restrict__ Q, const float* __restrict__ K,
                 const float* __restrict__ V, float* __restrict__ O) {
    extern __shared__ char sm[];
    const uint32_t sb = smem_u32(sm);
    const int tid = threadIdx.x;
    const int w = tid >> 5, t = tid & 31;
    const int c = blockIdx.x & (NCHUNK - 1);
    const int h = (blockIdx.x >> 6) & 15;
    const int b = blockIdx.x >> 10;

    const int ktA = (c == 0) ? 1 : 0;
    const int ktB = (c == NCHUNK - 1) ? 1 : 2;

    const float* Kb = K + (size_t)b * SEQ * HID + h * 64;
    const float* Vb = V + (size_t)b * SEQ * HID + h * 64;
    const int row0 = c * 128 - 128;

    // prefetch first tile while we process Q
    issue_cp_tile(sb, Kb + (size_t)(row0 + ktA * 128) * HID,
                      Vb + (size_t)(row0 + ktA * 128) * HID, tid);
    CP_COMMIT();

    load_split_q((const float4*)Q + ((size_t)b * SEQ + c * 128) * (HID / 4) + h * 16,
                 sm + OF_QH, sm + OF_QL, tid);
    __syncthreads();

    uint32_t qh[4][4], ql[4][4];
    {
        const uint32_t rowb = (uint32_t)((16 * w + (t & 15)) * 128 + ((t >> 4) & 1) * 16);
        #pragma unroll
        for (int kk = 0; kk < 4; kk++) {
            const uint32_t off = SWZ(rowb + kk * 32);
            ldsm4(qh[kk], sb + OF_QH + off);
            ldsm4(ql[kk], sb + OF_QL + off);
        }
    }

    float oacc[8][4];
    #pragma unroll
    for (int j = 0; j < 8; j++)
        #pragma unroll
        for (int r = 0; r < 4; r++) oacc[j][r] = 0.f;
    float l0 = 0.f, l1 = 0.f;
    const int i0 = 16 * w + (t >> 2);
    const int iB = i0 + 8;

    const uint32_t rb = (uint32_t)(((t & 7) + ((t >> 4) & 1) * 8) * 128 + ((t >> 3) & 1) * 16);
    const uint32_t vbo = (uint32_t)(((t & 7) + ((t >> 3) & 1) * 8) * 128 + ((t >> 4) & 1) * 16);

    for (int kt = ktA; kt <= ktB; kt++) {
        CP_WAIT0();
        __syncthreads();       // staging ready; previous tile's ldsm reads done
        convert_tile((const float*)(sm + OF_SK), sm + OF_KH, sm + OF_KL, tid);
        convert_tile((const float*)(sm + OF_SV), sm + OF_VH, sm + OF_VL, tid);
        __syncthreads();
        if (kt < ktB) {        // prefetch next tile; overlaps the GEMMs below
            issue_cp_tile(sb, Kb + (size_t)(row0 + (kt + 1) * 128) * HID,
                              Vb + (size_t)(row0 + (kt + 1) * 128) * HID, tid);
            CP_COMMIT();
        }

        // band-aware group bounds (warp-uniform)
        const int glo = (kt == 0) ? w : 0;
        const int ghi = (kt == 2) ? w : 7;

        #pragma unroll
        for (int g = 0; g < 8; g++) {
            if (g < glo || g > ghi) continue;

            // ---- QK^T for 16-key group g: S = Qh*Kh + Qh*Kl + Ql*Kh
            float acc[2][4];
            #pragma unroll
            for (int n = 0; n < 2; n++)
                #pragma unroll
                for (int r = 0; r < 4; r++) acc[n][r] = 0.f;
            #pragma unroll
            for (int kk = 0; kk < 4; kk++) {
                const uint32_t off = SWZ(rb + g * 2048 + kk * 32);
                uint32_t bh[4], bl[4];
                ldsm4(bh, sb + OF_KH + off);
                ldsm4(bl, sb + OF_KL + off);
                mma_bf16(acc[0], qh[kk], bh[0], bh[1]);
                mma_bf16(acc[0], qh[kk], bl[0], bl[1]);
                mma_bf16(acc[0], ql[kk], bh[0], bh[1]);
                mma_bf16(acc[1], qh[kk], bh[2], bh[3]);
                mma_bf16(acc[1], qh[kk], bl[2], bl[3]);
                mma_bf16(acc[1], ql[kk], bh[2], bh[3]);
            }

            // ---- mask + exp (no-max softmax: exact; scores bounded)
            const int cg = kt * 128 + 16 * g + 2 * (t & 3);
            float p;
            p = (cg     >= i0 && cg     <= i0 + 256) ? __expf(acc[0][0]) : 0.f; acc[0][0] = p; l0 += p;
            p = (cg + 1 >= i0 && cg + 1 <= i0 + 256) ? __expf(acc[0][1]) : 0.f; acc[0][1] = p; l0 += p;
            p = (cg     >= iB && cg     <= iB + 256) ? __expf(acc[0][2]) : 0.f; acc[0][2] = p; l1 += p;
            p = (cg + 1 >= iB && cg + 1 <= iB + 256) ? __expf(acc[0][3]) : 0.f; acc[0][3] = p; l1 += p;
            p = (cg + 8 >= i0 && cg + 8 <= i0 + 256) ? __expf(acc[1][0]) : 0.f; acc[1][0] = p; l0 += p;
            p = (cg + 9 >= i0 && cg + 9 <= i0 + 256) ? __expf(acc[1][1]) : 0.f; acc[1][1] = p; l0 += p;
            p = (cg + 8 >= iB && cg + 8 <= iB + 256) ? __expf(acc[1][2]) : 0.f; acc[1][2] = p; l1 += p;
            p = (cg + 9 >= iB && cg + 9 <= iB + 256) ? __expf(acc[1][3]) : 0.f; acc[1][3] = p; l1 += p;

            // ---- split P to bf16 hi/lo A-fragments (registers only)
            uint32_t pah[4], pal[4];
            split2(acc[0][0], acc[0][1], pah[0], pal[0]);
            split2(acc[0][2], acc[0][3], pah[1], pal[1]);
            split2(acc[1][0], acc[1][1], pah[2], pal[2]);
            split2(acc[1][2], acc[1][3], pah[3], pal[3]);

            // ---- PV for group g: O += Ph*Vh + Ph*Vl + Pl*Vh
            #pragma unroll
            for (int u = 0; u < 4; u++) {
                const uint32_t off = SWZ(vbo + g * 2048 + u * 32);
                uint32_t vh[4], vl[4];
                ldsm4t(vh, sb + OF_VH + off);
                ldsm4t(vl, sb + OF_VL + off);
                mma_bf16(oacc[2 * u],     pah, vh[0], vh[1]);
                mma_bf16(oacc[2 * u],     pah, vl[0], vl[1]);
                mma_bf16(oacc[2 * u],     pal, vh[0], vh[1]);
                mma_bf16(oacc[2 * u + 1], pah, vh[2], vh[3]);
                mma_bf16(oacc[2 * u + 1], pah, vl[2], vl[3]);
                mma_bf16(oacc[2 * u + 1], pal, vh[2], vh[3]);
            }
        }
    }

    // ---- reduce row sums within the quad sharing these rows
    l0 += __shfl_xor_sync(0xffffffffu, l0, 1);
    l0 += __shfl_xor_sync(0xffffffffu, l0, 2);
    l1 += __shfl_xor_sync(0xffffffffu, l1, 1);
    l1 += __shfl_xor_sync(0xffffffffu, l1, 2);
    const float inv0 = 1.f / l0, inv1 = 1.f / l1;

    // ---- normalize + write
    float* Ob = O + ((size_t)b * SEQ + c * 128) * HID + h * 64;
    const int dcol = 2 * (t & 3);
    #pragma unroll
    for (int j = 0; j < 8; j++) {
        float2 v0 = make_float2(oacc[j][0] * inv0, oacc[j][1] * inv0);
        float2 v1 = make_float2(oacc[j][2] * inv1, oacc[j][3] * inv1);
        *(float2*)(Ob + (size_t)i0 * HID + 8 * j + dcol) = v0;
        *(float2*)(Ob + (size_t)(i0 + 8) * HID + 8 * j + dcol) = v1;
    }
}

extern "C" void kernel_launch(void* const* d_in, const int* in_sizes, int n_in,
                              void* d_out, int out_size) {
    const float* Q = (const float*)d_in[0];
    const float* K = (const float*)d_in[1];
    const float* V = (const float*)d_in[2];
    float* O = (float*)d_out;

    cudaFuncSetAttribute(swa_hmma2_kernel, cudaFuncAttributeMaxDynamicSharedMemorySize, SMEM_TOTAL);
    dim3 grid(2 * 16 * NCHUNK);   // 2048 blocks: (b, h, chunk)
    swa_hmma2_kernel<<<grid, THREADS, SMEM_TOTAL>>>(Q, K, V, O);
}

// round 13
// speedup vs baseline: 3.6789x; 1.3250x over previous
#include <cuda_runtime.h>
#include <cuda_bf16.h>
#include <cstdint>

#define SEQ     8192
#define HID     1024
#define NCHUNK  64
#define THREADS 256

// smem: 6 bf16 tiles [128 rows][64 d], 128 B/row, SW128-swizzled (16 KB each)
#define OF_QH 0
#define OF_QL 16384
#define OF_KH 32768
#define OF_KL 49152
#define OF_VH 65536
#define OF_VL 81920
#define SMEM_TOTAL 98304

__device__ __forceinline__ uint32_t smem_u32(const void* p) {
    uint32_t a;
    asm("{ .reg .u64 t; cvta.to.shared.u64 t, %1; cvt.u32.u64 %0, t; }" : "=r"(a) : "l"(p));
    return a;
}
__device__ __forceinline__ uint32_t SWZ(uint32_t x) { return x ^ ((x >> 3) & 0x70); }

__device__ __forceinline__ void ldsm4(uint32_t* r, uint32_t a) {
    asm volatile("ldmatrix.sync.aligned.m8n8.x4.shared.b16 {%0,%1,%2,%3}, [%4];"
        : "=r"(r[0]), "=r"(r[1]), "=r"(r[2]), "=r"(r[3]) : "r"(a));
}
__device__ __forceinline__ void ldsm4t(uint32_t* r, uint32_t a) {
    asm volatile("ldmatrix.sync.aligned.m8n8.x4.trans.shared.b16 {%0,%1,%2,%3}, [%4];"
        : "=r"(r[0]), "=r"(r[1]), "=r"(r[2]), "=r"(r[3]) : "r"(a));
}
__device__ __forceinline__ void mma_bf16(float* c, const uint32_t* a, uint32_t b0, uint32_t b1) {
    asm volatile("mma.sync.aligned.m16n8k16.row.col.f32.bf16.bf16.f32 "
        "{%0,%1,%2,%3}, {%4,%5,%6,%7}, {%8,%9}, {%0,%1,%2,%3};"
        : "+f"(c[0]), "+f"(c[1]), "+f"(c[2]), "+f"(c[3])
        : "r"(a[0]), "r"(a[1]), "r"(a[2]), "r"(a[3]), "r"(b0), "r"(b1));
}
__device__ __forceinline__ uint32_t pk_bf16(float lo, float hi) {
    uint32_t r; asm("cvt.rn.bf16x2.f32 %0, %1, %2;" : "=r"(r) : "f"(hi), "f"(lo)); return r;
}
__device__ __forceinline__ void split2(float a, float b, uint32_t& hi, uint32_t& lo) {
    hi = pk_bf16(a, b);
    float ra = a - __uint_as_float(hi << 16);
    float rb = b - __uint_as_float(hi & 0xffff0000u);
    lo = pk_bf16(ra, rb);
}

// Load [128 rows][64 d] fp32 tile from gmem, split to bf16 hi/lo, store SW128-swizzled.
__device__ __forceinline__ void load_split(const float4* g, char* smh, char* sml, int tid) {
    const int dg = tid & 7;        // 8-float d-group
    const int r0 = tid >> 3;       // 0..31
    #pragma unroll
    for (int rr = 0; rr < 4; rr++) {
        const int r = r0 + rr * 32;
        const float4* gp = g + (size_t)r * (HID / 4) + dg * 2;
        const float4 x0 = gp[0], x1 = gp[1];
        uint4 uh, ul;
        split2(x0.x, x0.y, uh.x, ul.x);
        split2(x0.z, x0.w, uh.y, ul.y);
        split2(x1.x, x1.y, uh.z, ul.z);
        split2(x1.z, x1.w, uh.w, ul.w);
        const uint32_t so = SWZ((uint32_t)(r * 128 + dg * 16));
        *(uint4*)(smh + so) = uh;
        *(uint4*)(sml + so) = ul;
    }
}

// Block = (batch, head, 128-query chunk). 8 warps; warp w owns query rows [16w,16w+16).
// 2 CTAs/SM (96 KB smem, <=128 regs): sibling CTA's GEMMs hide this CTA's load phase.
// Per 16-key group: QK HMMAs -> mask+exp -> split P -> PV HMMAs, with B-fragment
// live ranges kept disjoint (bh used & dead before bl loads) for register pressure.
__global__ void __launch_bounds__(THREADS, 2)
swa_hmma3_kernel(const float* __restrict__ Q, const float* __restrict__ K,
                 const float* __restrict__ V, float* __restrict__ O) {
    extern __shared__ char sm[];
    const uint32_t sb = smem_u32(sm);
    const int tid = threadIdx.x;
    const int w = tid >> 5, t = tid & 31;
    const int c = blockIdx.x & (NCHUNK - 1);
    const int h = (blockIdx.x >> 6) & 15;
    const int b = blockIdx.x >> 10;

    // ---- Q chunk -> smem (hi/lo), then A-fragments into registers
    load_split((const float4*)Q + ((size_t)b * SEQ + c * 128) * (HID / 4) + h * 16,
               sm + OF_QH, sm + OF_QL, tid);
    __syncthreads();

    uint32_t qh[4][4], ql[4][4];
    {
        const uint32_t rowb = (uint32_t)((16 * w + (t & 15)) * 128 + ((t >> 4) & 1) * 16);
        #pragma unroll
        for (int kk = 0; kk < 4; kk++) {
            const uint32_t off = SWZ(rowb + kk * 32);
            ldsm4(qh[kk], sb + OF_QH + off);
            ldsm4(ql[kk], sb + OF_QL + off);
        }
    }

    float oacc[8][4];
    #pragma unroll
    for (int j = 0; j < 8; j++)
        #pragma unroll
        for (int r = 0; r < 4; r++) oacc[j][r] = 0.f;
    float l0 = 0.f, l1 = 0.f;
    const int i0 = 16 * w + (t >> 2);
    const int iB = i0 + 8;

    const uint32_t rb  = (uint32_t)(((t & 7) + ((t >> 4) & 1) * 8) * 128 + ((t >> 3) & 1) * 16);
    const uint32_t vbo = (uint32_t)(((t & 7) + ((t >> 3) & 1) * 8) * 128 + ((t >> 4) & 1) * 16);

    const int ktA = (c == 0) ? 1 : 0;
    const int ktB = (c == NCHUNK - 1) ? 1 : 2;

    for (int kt = ktA; kt <= ktB; kt++) {
        __syncthreads();   // previous tile's ldmatrix reads done before overwrite
        const int kbase = c * 128 - 128 + kt * 128;   // fully in-range (edge tiles skipped)
        load_split((const float4*)K + ((size_t)b * SEQ + kbase) * (HID / 4) + h * 16,
                   sm + OF_KH, sm + OF_KL, tid);
        load_split((const float4*)V + ((size_t)b * SEQ + kbase) * (HID / 4) + h * 16,
                   sm + OF_VH, sm + OF_VL, tid);
        __syncthreads();

        // band-aware group bounds (warp-uniform)
        const int glo = (kt == 0) ? w : 0;
        const int ghi = (kt == 2) ? w : 7;

        #pragma unroll 1
        for (int g = glo; g <= ghi; g++) {
            // ---- QK^T for 16-key group g: S = Qh*Kh + Ql*Kh + Qh*Kl
            float acc[2][4];
            #pragma unroll
            for (int n = 0; n < 2; n++)
                #pragma unroll
                for (int r = 0; r < 4; r++) acc[n][r] = 0.f;
            #pragma unroll
            for (int kk = 0; kk < 4; kk++) {
                const uint32_t off = SWZ(rb + (uint32_t)g * 2048 + kk * 32);
                {   // bh live range
                    uint32_t bh[4];
                    ldsm4(bh, sb + OF_KH + off);
                    mma_bf16(acc[0], qh[kk], bh[0], bh[1]);
                    mma_bf16(acc[1], qh[kk], bh[2], bh[3]);
                    mma_bf16(acc[0], ql[kk], bh[0], bh[1]);
                    mma_bf16(acc[1], ql[kk], bh[2], bh[3]);
                }
                {   // bl live range (bh dead)
                    uint32_t bl[4];
                    ldsm4(bl, sb + OF_KL + off);
                    mma_bf16(acc[0], qh[kk], bl[0], bl[1]);
                    mma_bf16(acc[1], qh[kk], bl[2], bl[3]);
                }
            }

            // ---- mask + exp (no-max softmax: exact; scores bounded)
            const int cg = kt * 128 + 16 * g + 2 * (t & 3);
            float p;
            p = (cg     >= i0 && cg     <= i0 + 256) ? __expf(acc[0][0]) : 0.f; acc[0][0] = p; l0 += p;
            p = (cg + 1 >= i0 && cg + 1 <= i0 + 256) ? __expf(acc[0][1]) : 0.f; acc[0][1] = p; l0 += p;
            p = (cg     >= iB && cg     <= iB + 256) ? __expf(acc[0][2]) : 0.f; acc[0][2] = p; l1 += p;
            p = (cg + 1 >= iB && cg + 1 <= iB + 256) ? __expf(acc[0][3]) : 0.f; acc[0][3] = p; l1 += p;
            p = (cg + 8 >= i0 && cg + 8 <= i0 + 256) ? __expf(acc[1][0]) : 0.f; acc[1][0] = p; l0 += p;
            p = (cg + 9 >= i0 && cg + 9 <= i0 + 256) ? __expf(acc[1][1]) : 0.f; acc[1][1] = p; l0 += p;
            p = (cg + 8 >= iB && cg + 8 <= iB + 256) ? __expf(acc[1][2]) : 0.f; acc[1][2] = p; l1 += p;
            p = (cg + 9 >= iB && cg + 9 <= iB + 256) ? __expf(acc[1][3]) : 0.f; acc[1][3] = p; l1 += p;

            // ---- split P to bf16 hi/lo A-fragments (registers only)
            uint32_t pah[4], pal[4];
            split2(acc[0][0], acc[0][1], pah[0], pal[0]);
            split2(acc[0][2], acc[0][3], pah[1], pal[1]);
            split2(acc[1][0], acc[1][1], pah[2], pal[2]);
            split2(acc[1][2], acc[1][3], pah[3], pal[3]);

            // ---- PV for group g: O += Ph*Vh + Pl*Vh + Ph*Vl
            #pragma unroll
            for (int u = 0; u < 4; u++) {
                const uint32_t off = SWZ(vbo + (uint32_t)g * 2048 + u * 32);
                {   // vh live range
                    uint32_t vh[4];
                    ldsm4t(vh, sb + OF_VH + off);
                    mma_bf16(oacc[2 * u],     pah, vh[0], vh[1]);
                    mma_bf16(oacc[2 * u + 1], pah, vh[2], vh[3]);
                    mma_bf16(oacc[2 * u],     pal, vh[0], vh[1]);
                    mma_bf16(oacc[2 * u + 1], pal, vh[2], vh[3]);
                }
                {   // vl live range (vh dead)
                    uint32_t vl[4];
                    ldsm4t(vl, sb + OF_VL + off);
                    mma_bf16(oacc[2 * u],     pah, vl[0], vl[1]);
                    mma_bf16(oacc[2 * u + 1], pah, vl[2], vl[3]);
                }
            }
        }
    }

    // ---- reduce row sums within the quad sharing these rows
    l0 += __shfl_xor_sync(0xffffffffu, l0, 1);
    l0 += __shfl_xor_sync(0xffffffffu, l0, 2);
    l1 += __shfl_xor_sync(0xffffffffu, l1, 1);
    l1 += __shfl_xor_sync(0xffffffffu, l1, 2);
    const float inv0 = 1.f / l0, inv1 = 1.f / l1;

    // ---- normalize + write
    float* Ob = O + ((size_t)b * SEQ + c * 128) * HID + h * 64;
    const int dcol = 2 * (t & 3);
    #pragma unroll
    for (int j = 0; j < 8; j++) {
        float2 v0 = make_float2(oacc[j][0] * inv0, oacc[j][1] * inv0);
        float2 v1 = make_float2(oacc[j][2] * inv1, oacc[j][3] * inv1);
        *(float2*)(Ob + (size_t)i0 * HID + 8 * j + dcol) = v0;
        *(float2*)(Ob + (size_t)(i0 + 8) * HID + 8 * j + dcol) = v1;
    }
}

extern "C" void kernel_launch(void* const* d_in, const int* in_sizes, int n_in,
                              void* d_out, int out_size) {
    const float* Q = (const float*)d_in[0];
    const float* K = (const float*)d_in[1];
    const float* V = (const float*)d_in[2];
    float* O = (float*)d_out;

    cudaFuncSetAttribute(swa_hmma3_kernel, cudaFuncAttributeMaxDynamicSharedMemorySize, SMEM_TOTAL);
    dim3 grid(2 * 16 * NCHUNK);   // 2048 blocks: (b, h, chunk)
    swa_hmma3_kernel<<<grid, THREADS, SMEM_TOTAL>>>(Q, K, V, O);
}